// round 1
// baseline (speedup 1.0000x reference)
#include <cuda_runtime.h>
#include <math.h>

// ---------------- problem constants ----------------
#define S    256      // tokens
#define Dm   2048     // model dim
#define NH   16
#define DH   128
#define MLPD 8192
#define INPUT_D 4096
#define EPS  1e-5f

// ---------------- scratch (device globals; no allocation) ----------------
__device__ float g_x  [S * Dm];        // residual stream
__device__ float g_h  [S * Dm];        // layernorm output
__device__ float g_q  [S * Dm];
__device__ float g_k  [S * Dm];
__device__ float g_v  [S * Dm];
__device__ float g_att[NH * S * S];    // attention probs
__device__ float g_m  [S * MLPD];      // MLP intermediate

// ---------------- generic tiled fp32 GEMM ----------------
// C[M,N] = epilogue( scale * A[M,K] (*) B + bias ), optionally transposed B,
// optionally batched via blockIdx.z pointer offsets.
// modes: 0 = store (val)            1 = store (val + posemb(m,n))
//        2 = store gelu(val)        3 = C += val   (residual accumulate)
#define BM 64
#define BN 64
#define BK 16

__global__ __launch_bounds__(256) void sgemm_k(
    const float* __restrict__ A, const float* __restrict__ B, float* __restrict__ C,
    int M, int N, int K, int lda, int ldb, int ldc,
    long batchA, long batchB, long batchC,
    const float* __restrict__ bias, long biasBatch,
    float scale, int mode, int transB)
{
    __shared__ float As[BK][BM];
    __shared__ float Bs[BK][BN];

    const int bz = blockIdx.z;
    A += (long)bz * batchA;
    B += (long)bz * batchB;
    C += (long)bz * batchC;
    if (bias) bias += (long)bz * biasBatch;

    const int m0 = blockIdx.y * BM;
    const int n0 = blockIdx.x * BN;
    const int tid = threadIdx.x;
    const int tx = tid & 15;        // N direction (4 cols each)
    const int ty = tid >> 4;        // M direction (4 rows each)

    float acc[4][4] = {};

    const int aRow = tid >> 2;          // 0..63
    const int aCol = (tid & 3) << 2;    // 0,4,8,12

    for (int k0 = 0; k0 < K; k0 += BK) {
        // --- load A tile (BM x BK), store transposed into As[k][m]
        float4 av = *(const float4*)(A + (long)(m0 + aRow) * lda + k0 + aCol);
        As[aCol + 0][aRow] = av.x;
        As[aCol + 1][aRow] = av.y;
        As[aCol + 2][aRow] = av.z;
        As[aCol + 3][aRow] = av.w;

        // --- load B tile
        if (!transB) {
            const int bRow = tid >> 4;          // k: 0..15
            const int bCol = (tid & 15) << 2;   // n: 0..60
            float4 bv = *(const float4*)(B + (long)(k0 + bRow) * ldb + n0 + bCol);
            *(float4*)&Bs[bRow][bCol] = bv;
        } else {
            const int bRow = tid >> 2;          // n: 0..63
            const int bCol = (tid & 3) << 2;    // k: 0,4,8,12
            float4 bv = *(const float4*)(B + (long)(n0 + bRow) * ldb + k0 + bCol);
            Bs[bCol + 0][bRow] = bv.x;
            Bs[bCol + 1][bRow] = bv.y;
            Bs[bCol + 2][bRow] = bv.z;
            Bs[bCol + 3][bRow] = bv.w;
        }
        __syncthreads();

        #pragma unroll
        for (int kk = 0; kk < BK; kk++) {
            float4 a = *(const float4*)&As[kk][ty << 2];
            float4 b = *(const float4*)&Bs[kk][tx << 2];
            acc[0][0] += a.x * b.x; acc[0][1] += a.x * b.y; acc[0][2] += a.x * b.z; acc[0][3] += a.x * b.w;
            acc[1][0] += a.y * b.x; acc[1][1] += a.y * b.y; acc[1][2] += a.y * b.z; acc[1][3] += a.y * b.w;
            acc[2][0] += a.z * b.x; acc[2][1] += a.z * b.y; acc[2][2] += a.z * b.z; acc[2][3] += a.z * b.w;
            acc[3][0] += a.w * b.x; acc[3][1] += a.w * b.y; acc[3][2] += a.w * b.z; acc[3][3] += a.w * b.w;
        }
        __syncthreads();
    }

    #pragma unroll
    for (int i = 0; i < 4; i++) {
        const int m = m0 + (ty << 2) + i;
        #pragma unroll
        for (int j = 0; j < 4; j++) {
            const int n = n0 + (tx << 2) + j;
            float val = acc[i][j] * scale + (bias ? bias[n] : 0.0f);
            float* cp = C + (long)m * ldc + n;
            if (mode == 0) {
                *cp = val;
            } else if (mode == 1) {
                // positional embedding: even j -> sin, odd j -> cos
                int   even = ((n & 1) == 0);
                float expo = (even ? (float)n : (float)(n - 1)) / (float)Dm;
                float ang  = (float)m / powf(10000.0f, expo);
                *cp = val + (even ? sinf(ang) : cosf(ang));
            } else if (mode == 2) {
                // exact GELU: 0.5*x*(1+erf(x/sqrt(2)))
                *cp = 0.5f * val * (1.0f + erff(val * 0.70710678118654752f));
            } else { // mode == 3
                *cp += val;
            }
        }
    }
}

// ---------------- layernorm (one block per row, 256 threads) ----------------
__global__ __launch_bounds__(256) void layernorm_k(
    const float* __restrict__ x, float* __restrict__ y,
    const float* __restrict__ g, const float* __restrict__ b)
{
    const int row = blockIdx.x;
    const float* xr = x + (long)row * Dm;
    const int t = threadIdx.x;
    __shared__ float red[256];

    float loc[8];
    float s = 0.f;
    #pragma unroll
    for (int i = 0; i < 8; i++) { loc[i] = xr[t + i * 256]; s += loc[i]; }

    red[t] = s; __syncthreads();
    for (int st = 128; st > 0; st >>= 1) { if (t < st) red[t] += red[t + st]; __syncthreads(); }
    const float mean = red[0] * (1.0f / Dm);
    __syncthreads();

    float vs = 0.f;
    #pragma unroll
    for (int i = 0; i < 8; i++) { float d = loc[i] - mean; vs += d * d; }
    red[t] = vs; __syncthreads();
    for (int st = 128; st > 0; st >>= 1) { if (t < st) red[t] += red[t + st]; __syncthreads(); }
    const float inv = rsqrtf(red[0] * (1.0f / Dm) + EPS);

    float* yr = y + (long)row * Dm;
    #pragma unroll
    for (int i = 0; i < 8; i++) {
        const int c = t + i * 256;
        yr[c] = (loc[i] - mean) * inv * g[c] + b[c];
    }
}

// ---------------- softmax over rows of length 256 ----------------
__global__ __launch_bounds__(256) void softmax_k(float* __restrict__ att)
{
    const int row = blockIdx.x;
    float* p = att + (long)row * 256;
    const int t = threadIdx.x;
    __shared__ float red[256];

    float v = p[t];
    red[t] = v; __syncthreads();
    for (int st = 128; st > 0; st >>= 1) { if (t < st) red[t] = fmaxf(red[t], red[t + st]); __syncthreads(); }
    const float mx = red[0];
    __syncthreads();

    float e = expf(v - mx);
    red[t] = e; __syncthreads();
    for (int st = 128; st > 0; st >>= 1) { if (t < st) red[t] += red[t + st]; __syncthreads(); }
    p[t] = e / red[0];
}

// ---------------- head: sigmoid(x[0] . head_w + head_b); copy memory ----------------
__global__ __launch_bounds__(256) void head_k(
    const float* __restrict__ x, const float* __restrict__ hw,
    const float* __restrict__ hb, const float* __restrict__ mem,
    float* __restrict__ out, int memN)
{
    const int t = threadIdx.x;
    __shared__ float red[256];
    float s = 0.f;
    for (int i = t; i < Dm; i += 256) s += x[i] * hw[i];
    red[t] = s; __syncthreads();
    for (int st = 128; st > 0; st >>= 1) { if (t < st) red[t] += red[t + st]; __syncthreads(); }
    if (t == 0) {
        float z = red[0] + hb[0];
        out[0] = 1.0f / (1.0f + expf(-z));
    }
    if (t >= 1 && t <= memN) out[t] = mem[t - 1];
}

// ---------------- host launcher ----------------
static inline float* symaddr(const void* sym) {
    void* p = nullptr;
    cudaGetSymbolAddress(&p, sym);
    return (float*)p;
}

extern "C" void kernel_launch(void* const* d_in, const int* in_sizes, int n_in,
                              void* d_out, int out_size)
{
    const float* images = (const float*)d_in[0];
    const float* memory = (const float*)d_in[1];
    const float* wmap   = (const float*)d_in[2];
    const float* bmap   = (const float*)d_in[3];
    const float* ln1_g  = (const float*)d_in[4];
    const float* ln1_b  = (const float*)d_in[5];
    const float* qw     = (const float*)d_in[6];
    const float* qb     = (const float*)d_in[7];
    const float* kw     = (const float*)d_in[8];
    const float* kb     = (const float*)d_in[9];
    const float* vw     = (const float*)d_in[10];
    const float* vb     = (const float*)d_in[11];
    const float* ln2_g  = (const float*)d_in[12];
    const float* ln2_b  = (const float*)d_in[13];
    const float* w1     = (const float*)d_in[14];
    const float* b1     = (const float*)d_in[15];
    const float* w2     = (const float*)d_in[16];
    const float* b2     = (const float*)d_in[17];
    const float* head_w = (const float*)d_in[18];
    const float* head_b = (const float*)d_in[19];
    float* out = (float*)d_out;

    float* x   = symaddr(g_x);
    float* h   = symaddr(g_h);
    float* q   = symaddr(g_q);
    float* k   = symaddr(g_k);
    float* v   = symaddr(g_v);
    float* att = symaddr(g_att);
    float* m   = symaddr(g_m);

    const float attScale = 1.0f / sqrtf((float)DH);

    // patch embed: x = images(reshaped 256x4096) @ wmap + bmap + posemb
    sgemm_k<<<dim3(Dm / BN, S / BM, 1), 256>>>(
        images, wmap, x, S, Dm, INPUT_D, INPUT_D, Dm, Dm,
        0, 0, 0, bmap, 0, 1.0f, /*mode=*/1, /*transB=*/0);

    for (int l = 0; l < 2; l++) {
        const long wOff  = (long)l * NH * DH * DH;
        const long bOff  = (long)l * Dm;
        const long w1Off = (long)l * Dm * MLPD;
        const long w2Off = (long)l * MLPD * Dm;

        // h = LN1(x)
        layernorm_k<<<S, 256>>>(x, h, ln1_g + bOff, ln1_b + bOff);

        // q,k,v : per-head 256x128x128 batched GEMMs
        sgemm_k<<<dim3(DH / BN, S / BM, NH), 256>>>(
            h, qw + wOff, q, S, DH, DH, Dm, DH, Dm,
            DH, (long)DH * DH, DH, qb + bOff, DH, 1.0f, 0, 0);
        sgemm_k<<<dim3(DH / BN, S / BM, NH), 256>>>(
            h, kw + wOff, k, S, DH, DH, Dm, DH, Dm,
            DH, (long)DH * DH, DH, kb + bOff, DH, 1.0f, 0, 0);
        sgemm_k<<<dim3(DH / BN, S / BM, NH), 256>>>(
            h, vw + wOff, v, S, DH, DH, Dm, DH, Dm,
            DH, (long)DH * DH, DH, vb + bOff, DH, 1.0f, 0, 0);

        // scores = q @ k^T / sqrt(DH)  (per head, NT)
        sgemm_k<<<dim3(S / BN, S / BM, NH), 256>>>(
            q, k, att, S, S, DH, Dm, Dm, S,
            DH, DH, (long)S * S, nullptr, 0, attScale, 0, /*transB=*/1);

        // softmax per row
        softmax_k<<<NH * S, 256>>>(att);

        // x += att @ v   (per head, accumulate into residual)
        sgemm_k<<<dim3(DH / BN, S / BM, NH), 256>>>(
            att, v, x, S, DH, S, S, Dm, Dm,
            (long)S * S, DH, DH, nullptr, 0, 1.0f, /*mode=*/3, 0);

        // h = LN2(x)
        layernorm_k<<<S, 256>>>(x, h, ln2_g + bOff, ln2_b + bOff);

        // m = gelu(h @ w1 + b1)
        sgemm_k<<<dim3(MLPD / BN, S / BM, 1), 256>>>(
            h, w1 + w1Off, m, S, MLPD, Dm, Dm, MLPD, MLPD,
            0, 0, 0, b1 + (long)l * MLPD, 0, 1.0f, /*mode=*/2, 0);

        // x += m @ w2 + b2
        sgemm_k<<<dim3(Dm / BN, S / BM, 1), 256>>>(
            m, w2 + w2Off, x, S, Dm, MLPD, MLPD, Dm, Dm,
            0, 0, 0, b2 + bOff, 0, 1.0f, /*mode=*/3, 0);
    }

    // head
    int memN = in_sizes[1];
    if (memN > out_size - 1) memN = out_size - 1;
    head_k<<<1, 256>>>(x, head_w, head_b, memory, out, memN);
}

// round 2
// speedup vs baseline: 2.7257x; 2.7257x over previous
#include <cuda_runtime.h>
#include <math.h>

// ---------------- problem constants ----------------
#define S    256
#define Dm   2048
#define NH   16
#define DH   128
#define MLPD 8192
#define INPUT_D 4096
#define EPS  1e-5f

// ---------------- scratch (device globals; no allocation) ----------------
__device__ float g_x  [S * Dm];
__device__ float g_h  [S * Dm];
__device__ float g_q  [S * Dm];
__device__ float g_k  [S * Dm];
__device__ float g_v  [S * Dm];
__device__ float g_att[NH * S * S];
__device__ float g_m  [S * MLPD];
__device__ float g_split[4 * S * Dm];   // split-K partials (max N = 2048)

// ---------------- tf32 tensor-core GEMM ----------------
// C[M,N] = epilogue( scale * A[M,K] (*) B + bias )
// transB: 0 -> B[K,N] row-major ; 1 -> B[N,K] row-major (i.e. C = A B^T)
// modes: 0 store | 1 store+posemb | 2 gelu | 3 accumulate | -1 raw (split-K)
#define BM 128
#define BN 128
#define BK 32
#define LDA_S 36    // As stride (BK+4):  36 % 32 == 4  -> conflict-free frags
#define LDB_S 136   // Bs stride (BN+8): 136 % 32 == 8  -> conflict-free frags

__device__ __forceinline__ float f2tf32(float x) {
    unsigned u;
    asm("cvt.rna.tf32.f32 %0, %1;" : "=r"(u) : "f"(x));
    return __uint_as_float(u);
}

__device__ __forceinline__ void mma_tf32(float* c, const float* a, const float* b) {
    const unsigned* A = reinterpret_cast<const unsigned*>(a);
    const unsigned* B = reinterpret_cast<const unsigned*>(b);
    asm volatile(
        "mma.sync.aligned.m16n8k8.row.col.f32.tf32.tf32.f32 "
        "{%0,%1,%2,%3}, {%4,%5,%6,%7}, {%8,%9}, {%0,%1,%2,%3};\n"
        : "+f"(c[0]), "+f"(c[1]), "+f"(c[2]), "+f"(c[3])
        : "r"(A[0]), "r"(A[1]), "r"(A[2]), "r"(A[3]), "r"(B[0]), "r"(B[1]));
}

__global__ __launch_bounds__(256) void tgemm_k(
    const float* __restrict__ A, const float* __restrict__ B, float* __restrict__ C,
    int M, int N, int K, int lda, int ldb, int ldc,
    long batchA, long batchB, long batchC,
    const float* __restrict__ bias, long biasBatch,
    float scale, int mode, int transB, int splitK)
{
    __shared__ float As[BM * LDA_S];   // m-major [m][k]
    __shared__ float Bs[BK * LDB_S];   // k-major [k][n]

    const int z = blockIdx.z;
    if (splitK > 1) {
        const int Kc = K / splitK;
        A += (long)z * Kc;
        B += transB ? (long)z * Kc : (long)z * Kc * ldb;
        C += (long)z * M * N;
        ldc = N;
        K = Kc;
        bias = nullptr;
        mode = -1;
    } else {
        A += (long)z * batchA;
        B += (long)z * batchB;
        C += (long)z * batchC;
        if (bias) bias += (long)z * biasBatch;
    }

    const int m0 = blockIdx.y * BM;
    const int n0 = blockIdx.x * BN;
    const int tid  = threadIdx.x;
    const int lane = tid & 31;
    const int warp = tid >> 5;
    const int wm = warp >> 2;          // 0..1  (rows, 64 each)
    const int wn = warp & 3;           // 0..3  (cols, 32 each)
    const int lr = lane >> 2;          // 0..7
    const int lc = lane & 3;           // 0..3

    float acc[4][4][4];
    #pragma unroll
    for (int i = 0; i < 4; i++)
        #pragma unroll
        for (int j = 0; j < 4; j++)
            #pragma unroll
            for (int r = 0; r < 4; r++) acc[i][j][r] = 0.f;

    float ra[16], rb[16];

    // precomputed staging indices
    const int aM  = (tid >> 3);          // row in tile (two chunks of 128? no: 256 thr * 4 iters)
    const int aKq = (tid & 7) << 2;      // k quad
    const int bK  = (tid >> 5);          // transB=0: k row (chunks)
    const int bNq = (tid & 31) << 2;     // transB=0: n quad
    const int bN  = (tid >> 3);          // transB=1: n row
    const int bKq = (tid & 7) << 2;      // transB=1: k quad

    const int nK = K / BK;

    // ---- prologue: load tile 0 into registers ----
    {
        #pragma unroll
        for (int i = 0; i < 4; i++) {
            const int m = aM + i * 32;
            float4 v = *(const float4*)(A + (long)(m0 + m) * lda + aKq);
            ra[i*4+0] = f2tf32(v.x); ra[i*4+1] = f2tf32(v.y);
            ra[i*4+2] = f2tf32(v.z); ra[i*4+3] = f2tf32(v.w);
        }
        if (!transB) {
            #pragma unroll
            for (int i = 0; i < 4; i++) {
                const int k = bK + i * 8;
                float4 v = *(const float4*)(B + (long)k * ldb + n0 + bNq);
                rb[i*4+0] = f2tf32(v.x); rb[i*4+1] = f2tf32(v.y);
                rb[i*4+2] = f2tf32(v.z); rb[i*4+3] = f2tf32(v.w);
            }
        } else {
            #pragma unroll
            for (int i = 0; i < 4; i++) {
                const int n = bN + i * 32;
                float4 v = *(const float4*)(B + (long)(n0 + n) * ldb + bKq);
                rb[i*4+0] = f2tf32(v.x); rb[i*4+1] = f2tf32(v.y);
                rb[i*4+2] = f2tf32(v.z); rb[i*4+3] = f2tf32(v.w);
            }
        }
    }

    for (int kt = 0; kt < nK; kt++) {
        __syncthreads();   // previous compute finished; safe to overwrite smem
        // ---- store staged regs -> smem ----
        #pragma unroll
        for (int i = 0; i < 4; i++) {
            const int m = aM + i * 32;
            *(float4*)&As[m * LDA_S + aKq] = make_float4(ra[i*4+0], ra[i*4+1], ra[i*4+2], ra[i*4+3]);
        }
        if (!transB) {
            #pragma unroll
            for (int i = 0; i < 4; i++) {
                const int k = bK + i * 8;
                *(float4*)&Bs[k * LDB_S + bNq] = make_float4(rb[i*4+0], rb[i*4+1], rb[i*4+2], rb[i*4+3]);
            }
        } else {
            #pragma unroll
            for (int i = 0; i < 4; i++) {
                const int n = bN + i * 32;
                #pragma unroll
                for (int j = 0; j < 4; j++) Bs[(bKq + j) * LDB_S + n] = rb[i*4+j];
            }
        }
        __syncthreads();

        // ---- prefetch next tile into regs (LDG latency hidden by compute) ----
        if (kt + 1 < nK) {
            const int k0 = (kt + 1) * BK;
            #pragma unroll
            for (int i = 0; i < 4; i++) {
                const int m = aM + i * 32;
                float4 v = *(const float4*)(A + (long)(m0 + m) * lda + k0 + aKq);
                ra[i*4+0] = f2tf32(v.x); ra[i*4+1] = f2tf32(v.y);
                ra[i*4+2] = f2tf32(v.z); ra[i*4+3] = f2tf32(v.w);
            }
            if (!transB) {
                #pragma unroll
                for (int i = 0; i < 4; i++) {
                    const int k = bK + i * 8;
                    float4 v = *(const float4*)(B + (long)(k0 + k) * ldb + n0 + bNq);
                    rb[i*4+0] = f2tf32(v.x); rb[i*4+1] = f2tf32(v.y);
                    rb[i*4+2] = f2tf32(v.z); rb[i*4+3] = f2tf32(v.w);
                }
            } else {
                #pragma unroll
                for (int i = 0; i < 4; i++) {
                    const int n = bN + i * 32;
                    float4 v = *(const float4*)(B + (long)(n0 + n) * ldb + k0 + bKq);
                    rb[i*4+0] = f2tf32(v.x); rb[i*4+1] = f2tf32(v.y);
                    rb[i*4+2] = f2tf32(v.z); rb[i*4+3] = f2tf32(v.w);
                }
            }
        }

        // ---- compute: 4 k-steps of 8 ----
        #pragma unroll
        for (int ks = 0; ks < BK; ks += 8) {
            float af[4][4], bf[4][2];
            #pragma unroll
            for (int mt = 0; mt < 4; mt++) {
                const int rm = wm * 64 + mt * 16;
                af[mt][0] = As[(rm + lr    ) * LDA_S + ks + lc    ];
                af[mt][1] = As[(rm + lr + 8) * LDA_S + ks + lc    ];
                af[mt][2] = As[(rm + lr    ) * LDA_S + ks + lc + 4];
                af[mt][3] = As[(rm + lr + 8) * LDA_S + ks + lc + 4];
            }
            #pragma unroll
            for (int nt = 0; nt < 4; nt++) {
                const int cn = wn * 32 + nt * 8 + lr;
                bf[nt][0] = Bs[(ks + lc    ) * LDB_S + cn];
                bf[nt][1] = Bs[(ks + lc + 4) * LDB_S + cn];
            }
            #pragma unroll
            for (int mt = 0; mt < 4; mt++)
                #pragma unroll
                for (int nt = 0; nt < 4; nt++)
                    mma_tf32(acc[mt][nt], af[mt], bf[nt]);
        }
    }

    // ---- epilogue ----
    #pragma unroll
    for (int mt = 0; mt < 4; mt++) {
        #pragma unroll
        for (int nt = 0; nt < 4; nt++) {
            #pragma unroll
            for (int half = 0; half < 2; half++) {
                const int r = m0 + wm * 64 + mt * 16 + lr + half * 8;
                const int cbase = n0 + wn * 32 + nt * 8 + lc * 2;
                #pragma unroll
                for (int j = 0; j < 2; j++) {
                    const int n = cbase + j;
                    float raw = acc[mt][nt][half * 2 + j];
                    float* cp = C + (long)r * ldc + n;
                    if (mode == -1) { *cp = raw; continue; }
                    float val = raw * scale + (bias ? bias[n] : 0.0f);
                    if (mode == 0) *cp = val;
                    else if (mode == 1) {
                        int   even = ((n & 1) == 0);
                        float expo = (even ? (float)n : (float)(n - 1)) / (float)Dm;
                        float ang  = (float)r / powf(10000.0f, expo);
                        *cp = val + (even ? sinf(ang) : cosf(ang));
                    } else if (mode == 2) {
                        *cp = 0.5f * val * (1.0f + erff(val * 0.70710678118654752f));
                    } else {
                        *cp += val;
                    }
                }
            }
        }
    }
}

// ---------------- split-K reduce + epilogue ----------------
__global__ __launch_bounds__(256) void reduce_k(
    const float* __restrict__ part, float* __restrict__ C,
    const float* __restrict__ bias, int M, int N, int ldc,
    int splitK, float scale, int mode)
{
    const int idx = blockIdx.x * 256 + threadIdx.x;
    if (idx >= M * N) return;
    const int m = idx / N;
    const int n = idx - m * N;
    float s = 0.f;
    for (int p = 0; p < splitK; p++) s += part[(long)p * M * N + idx];
    float val = s * scale + (bias ? bias[n] : 0.0f);
    float* cp = C + (long)m * ldc + n;
    if (mode == 0) *cp = val;
    else if (mode == 1) {
        int   even = ((n & 1) == 0);
        float expo = (even ? (float)n : (float)(n - 1)) / (float)Dm;
        float ang  = (float)m / powf(10000.0f, expo);
        *cp = val + (even ? sinf(ang) : cosf(ang));
    } else if (mode == 2) {
        *cp = 0.5f * val * (1.0f + erff(val * 0.70710678118654752f));
    } else {
        *cp += val;
    }
}

// ---------------- layernorm ----------------
__global__ __launch_bounds__(256) void layernorm_k(
    const float* __restrict__ x, float* __restrict__ y,
    const float* __restrict__ g, const float* __restrict__ b)
{
    const int row = blockIdx.x;
    const float* xr = x + (long)row * Dm;
    const int t = threadIdx.x;
    __shared__ float red[256];

    float loc[8];
    float s = 0.f;
    #pragma unroll
    for (int i = 0; i < 8; i++) { loc[i] = xr[t + i * 256]; s += loc[i]; }
    red[t] = s; __syncthreads();
    for (int st = 128; st > 0; st >>= 1) { if (t < st) red[t] += red[t + st]; __syncthreads(); }
    const float mean = red[0] * (1.0f / Dm);
    __syncthreads();

    float vs = 0.f;
    #pragma unroll
    for (int i = 0; i < 8; i++) { float d = loc[i] - mean; vs += d * d; }
    red[t] = vs; __syncthreads();
    for (int st = 128; st > 0; st >>= 1) { if (t < st) red[t] += red[t + st]; __syncthreads(); }
    const float inv = rsqrtf(red[0] * (1.0f / Dm) + EPS);

    float* yr = y + (long)row * Dm;
    #pragma unroll
    for (int i = 0; i < 8; i++) {
        const int c = t + i * 256;
        yr[c] = (loc[i] - mean) * inv * g[c] + b[c];
    }
}

// ---------------- softmax (rows of 256) ----------------
__global__ __launch_bounds__(256) void softmax_k(float* __restrict__ att)
{
    const int row = blockIdx.x;
    float* p = att + (long)row * 256;
    const int t = threadIdx.x;
    __shared__ float red[256];

    float v = p[t];
    red[t] = v; __syncthreads();
    for (int st = 128; st > 0; st >>= 1) { if (t < st) red[t] = fmaxf(red[t], red[t + st]); __syncthreads(); }
    const float mx = red[0];
    __syncthreads();

    float e = expf(v - mx);
    red[t] = e; __syncthreads();
    for (int st = 128; st > 0; st >>= 1) { if (t < st) red[t] += red[t + st]; __syncthreads(); }
    p[t] = e / red[0];
}

// ---------------- head ----------------
__global__ __launch_bounds__(256) void head_k(
    const float* __restrict__ x, const float* __restrict__ hw,
    const float* __restrict__ hb, const float* __restrict__ mem,
    float* __restrict__ out, int memN)
{
    const int t = threadIdx.x;
    __shared__ float red[256];
    float s = 0.f;
    for (int i = t; i < Dm; i += 256) s += x[i] * hw[i];
    red[t] = s; __syncthreads();
    for (int st = 128; st > 0; st >>= 1) { if (t < st) red[t] += red[t + st]; __syncthreads(); }
    if (t == 0) {
        float z = red[0] + hb[0];
        out[0] = 1.0f / (1.0f + expf(-z));
    }
    if (t >= 1 && t <= memN) out[t] = mem[t - 1];
}

// ---------------- host launcher ----------------
static inline float* symaddr(const void* sym) {
    void* p = nullptr;
    cudaGetSymbolAddress(&p, sym);
    return (float*)p;
}

extern "C" void kernel_launch(void* const* d_in, const int* in_sizes, int n_in,
                              void* d_out, int out_size)
{
    const float* images = (const float*)d_in[0];
    const float* memory = (const float*)d_in[1];
    const float* wmap   = (const float*)d_in[2];
    const float* bmap   = (const float*)d_in[3];
    const float* ln1_g  = (const float*)d_in[4];
    const float* ln1_b  = (const float*)d_in[5];
    const float* qw     = (const float*)d_in[6];
    const float* qb     = (const float*)d_in[7];
    const float* kw     = (const float*)d_in[8];
    const float* kb     = (const float*)d_in[9];
    const float* vw     = (const float*)d_in[10];
    const float* vb     = (const float*)d_in[11];
    const float* ln2_g  = (const float*)d_in[12];
    const float* ln2_b  = (const float*)d_in[13];
    const float* w1     = (const float*)d_in[14];
    const float* b1     = (const float*)d_in[15];
    const float* w2     = (const float*)d_in[16];
    const float* b2     = (const float*)d_in[17];
    const float* head_w = (const float*)d_in[18];
    const float* head_b = (const float*)d_in[19];
    float* out = (float*)d_out;

    float* x   = symaddr(g_x);
    float* h   = symaddr(g_h);
    float* q   = symaddr(g_q);
    float* k   = symaddr(g_k);
    float* v   = symaddr(g_v);
    float* att = symaddr(g_att);
    float* m   = symaddr(g_m);
    float* ws  = symaddr(g_split);

    const float attScale = 1.0f / sqrtf((float)DH);

    // ---- patch embed (split-K=4): x = images @ wmap + bmap + posemb ----
    tgemm_k<<<dim3(Dm / BN, S / BM, 4), 256>>>(
        images, wmap, ws, S, Dm, INPUT_D, INPUT_D, Dm, Dm,
        0, 0, 0, nullptr, 0, 1.0f, 0, 0, /*splitK=*/4);
    reduce_k<<<(S * Dm + 255) / 256, 256>>>(ws, x, bmap, S, Dm, Dm, 4, 1.0f, /*mode=*/1);

    for (int l = 0; l < 2; l++) {
        const long wOff  = (long)l * NH * DH * DH;
        const long bOff  = (long)l * Dm;
        const long w1Off = (long)l * Dm * MLPD;
        const long w2Off = (long)l * MLPD * Dm;

        layernorm_k<<<S, 256>>>(x, h, ln1_g + bOff, ln1_b + bOff);

        // q,k,v : batched per-head 256x128x128
        tgemm_k<<<dim3(DH / BN, S / BM, NH), 256>>>(
            h, qw + wOff, q, S, DH, DH, Dm, DH, Dm,
            DH, (long)DH * DH, DH, qb + bOff, DH, 1.0f, 0, 0, 1);
        tgemm_k<<<dim3(DH / BN, S / BM, NH), 256>>>(
            h, kw + wOff, k, S, DH, DH, Dm, DH, Dm,
            DH, (long)DH * DH, DH, kb + bOff, DH, 1.0f, 0, 0, 1);
        tgemm_k<<<dim3(DH / BN, S / BM, NH), 256>>>(
            h, vw + wOff, v, S, DH, DH, Dm, DH, Dm,
            DH, (long)DH * DH, DH, vb + bOff, DH, 1.0f, 0, 0, 1);

        // scores = q @ k^T / sqrt(DH)
        tgemm_k<<<dim3(S / BN, S / BM, NH), 256>>>(
            q, k, att, S, S, DH, Dm, Dm, S,
            DH, DH, (long)S * S, nullptr, 0, attScale, 0, /*transB=*/1, 1);

        softmax_k<<<NH * S, 256>>>(att);

        // x += att @ v
        tgemm_k<<<dim3(DH / BN, S / BM, NH), 256>>>(
            att, v, x, S, DH, S, S, Dm, Dm,
            (long)S * S, DH, DH, nullptr, 0, 1.0f, /*mode=*/3, 0, 1);

        layernorm_k<<<S, 256>>>(x, h, ln2_g + bOff, ln2_b + bOff);

        // m = gelu(h @ w1 + b1)
        tgemm_k<<<dim3(MLPD / BN, S / BM, 1), 256>>>(
            h, w1 + w1Off, m, S, MLPD, Dm, Dm, MLPD, MLPD,
            0, 0, 0, b1 + (long)l * MLPD, 0, 1.0f, /*mode=*/2, 0, 1);

        // x += m @ w2 + b2  (split-K=4)
        tgemm_k<<<dim3(Dm / BN, S / BM, 4), 256>>>(
            m, w2 + w2Off, ws, S, Dm, MLPD, MLPD, Dm, Dm,
            0, 0, 0, nullptr, 0, 1.0f, 0, 0, /*splitK=*/4);
        reduce_k<<<(S * Dm + 255) / 256, 256>>>(ws, x, b2 + bOff, S, Dm, Dm, 4, 1.0f, /*mode=*/3);
    }

    int memN = in_sizes[1];
    if (memN > out_size - 1) memN = out_size - 1;
    head_k<<<1, 256>>>(x, head_w, head_b, memory, out, memN);
}